// round 7
// baseline (speedup 1.0000x reference)
#include <cuda_runtime.h>
#include <math.h>

// RoPE-2D: x[B=32, S=1024, H=16, D=64] fp32, grid_sizes[B,2] int32.
// Combined rotation: rot(i*th) ∘ rot(j*th) == rot((i+j)*th).
// Persistent single-wave grid-stride kernel: 1184 CTAs (148 SM x 8),
// each iterates over 4-row chunks. 4 float4/thread per iter, loads
// front-batched; next iteration's loads overlap this iteration's stores.

#define F4_PER_ROW 16        // D=64 floats = 16 float4
#define S_LOG2 10
#define ROWS 4               // s-rows per chunk
#define NBLOCKS 1184         // 148 SMs * 8 CTAs: exactly one wave
#define NCHUNKS 8192         // 32768 rows / 4

__global__ void __launch_bounds__(256) rope2d_kernel(const float4* __restrict__ x,
                                                     const int* __restrict__ grid_sizes,
                                                     float4* __restrict__ out) {
    int tid = threadIdx.x;
    int t = tid & (F4_PER_ROW - 1);              // pairs k=2t, 2t+1

    // theta_k = 10000^(-k/32) = exp2(-k * log2(10000)/32)  (loop-invariant)
    const float C = 13.287712379549449f / 32.0f; // log2(10000)/32
    const float R = 0.7498942093324559f;         // 10000^(-1/32)
    float th0 = exp2f(-(float)(2 * t) * C);
    float th1 = th0 * R;

    for (int chunk = blockIdx.x; chunk < NCHUNKS; chunk += NBLOCKS) {
        int f0 = chunk * (ROWS * 256) + tid;

        // ---- front-batch the 4 streaming loads ----
        float4 v0 = __ldcs(&x[f0]);
        float4 v1 = __ldcs(&x[f0 + 256]);
        float4 v2 = __ldcs(&x[f0 + 512]);
        float4 v3 = __ldcs(&x[f0 + 768]);

        // ---- positions for the 4 consecutive s-rows (same b, same cols) ----
        unsigned row0 = (unsigned)chunk * ROWS;
        unsigned s = row0 & ((1u << S_LOG2) - 1u);
        unsigned b = row0 >> S_LOG2;
        unsigned cols = (unsigned)__ldg(&grid_sizes[2 * b + 1]);

        unsigned i = s / cols;                   // one division per chunk
        unsigned j = s - i * cols;
        int pos0 = (int)(i + j);
        j++; if (j == cols) { j = 0; i++; }
        int pos1 = (int)(i + j);
        j++; if (j == cols) { j = 0; i++; }
        int pos2 = (int)(i + j);
        j++; if (j == cols) { j = 0; i++; }
        int pos3 = (int)(i + j);

#define ROTATE_STORE(v, p, off)                                   \
        do {                                                      \
            float ca, sa, cb, sb;                                 \
            __sincosf((float)(p) * th0, &sa, &ca);                \
            __sincosf((float)(p) * th1, &sb, &cb);                \
            float4 o;                                             \
            o.x = fmaf((v).x, ca, -(v).y * sa);                   \
            o.y = fmaf((v).y, ca,  (v).x * sa);                   \
            o.z = fmaf((v).z, cb, -(v).w * sb);                   \
            o.w = fmaf((v).w, cb,  (v).z * sb);                   \
            __stcs(&out[f0 + (off)], o);                          \
        } while (0)

        ROTATE_STORE(v0, pos0, 0);
        ROTATE_STORE(v1, pos1, 256);
        ROTATE_STORE(v2, pos2, 512);
        ROTATE_STORE(v3, pos3, 768);
#undef ROTATE_STORE
    }
}

extern "C" void kernel_launch(void* const* d_in, const int* in_sizes, int n_in,
                              void* d_out, int out_size) {
    const float4* x = (const float4*)d_in[0];
    const int* grid_sizes = (const int*)d_in[1];
    float4* out = (float4*)d_out;

    rope2d_kernel<<<NBLOCKS, 256>>>(x, grid_sizes, out);
}

// round 8
// speedup vs baseline: 1.0993x; 1.0993x over previous
#include <cuda_runtime.h>
#include <math.h>

// RoPE-2D: x[B=32, S=1024, H=16, D=64] fp32, grid_sizes[B,2] int32.
// Combined rotation: rot(i*th) ∘ rot(j*th) == rot((i+j)*th).
// One-shot grid (best config from R4), 4 float4/thread, loads front-batched,
// per-thread fast-math sincos hidden under load latency. Block=128 to halve
// the CTA tail quantum and smooth per-SMSP warp supply (16 CTAs/SM ceiling).

#define F4_PER_ROW 16        // D=64 floats = 16 float4
#define S_LOG2 10

__global__ void __launch_bounds__(128) rope2d_kernel(const float4* __restrict__ x,
                                                     const int* __restrict__ grid_sizes,
                                                     float4* __restrict__ out) {
    int tid = threadIdx.x;                 // 0..127
    int f0 = blockIdx.x * 512 + tid;       // 2 rows per 128 threads * 4 = ...
    // layout: each block covers 512 consecutive float4 = 2 s-rows,
    // thread handles f0, f0+128, f0+256, f0+384 (rows r0,r0,r1,r1? no:)
    // 512 float4 = 2 rows of 256. tid in [0,128): f0 in row0 first half,
    // f0+128 row0 second half, f0+256 row1 first half, f0+384 row1 second half.

    // ---- front-batch the 4 streaming loads (MLP_p1 = 4) ----
    float4 v0 = __ldcs(&x[f0]);
    float4 v1 = __ldcs(&x[f0 + 128]);
    float4 v2 = __ldcs(&x[f0 + 256]);
    float4 v3 = __ldcs(&x[f0 + 384]);

    // ---- positions for the 2 consecutive s-rows (same b, same cols) ----
    unsigned row0 = blockIdx.x * 2;
    unsigned s = row0 & ((1u << S_LOG2) - 1u);
    unsigned b = row0 >> S_LOG2;
    unsigned cols = (unsigned)__ldg(&grid_sizes[2 * b + 1]);

    unsigned i = s / cols;                 // one division for both rows
    unsigned j = s - i * cols;
    int pos0 = (int)(i + j);
    int pos1 = (j + 1u < cols) ? pos0 + 1 : (int)(i + 1u);

    // theta_k = 10000^(-k/32) = exp2(-k * log2(10000)/32)
    int t = tid & (F4_PER_ROW - 1);        // pairs k=2t, 2t+1
    const float C = 13.287712379549449f / 32.0f;   // log2(10000)/32
    const float R = 0.7498942093324559f;           // 10000^(-1/32)
    float th0 = exp2f(-(float)(2 * t) * C);
    float th1 = th0 * R;

    // v0,v1 belong to row0 (pos0); v2,v3 belong to row1 (pos1).
    float c00, s00, c01, s01, c10, s10, c11, s11;
    __sincosf((float)pos0 * th0, &s00, &c00);
    __sincosf((float)pos0 * th1, &s01, &c01);
    __sincosf((float)pos1 * th0, &s10, &c10);
    __sincosf((float)pos1 * th1, &s11, &c11);

    float4 o0, o1, o2, o3;
    o0.x = fmaf(v0.x, c00, -v0.y * s00);
    o0.y = fmaf(v0.y, c00,  v0.x * s00);
    o0.z = fmaf(v0.z, c01, -v0.w * s01);
    o0.w = fmaf(v0.w, c01,  v0.z * s01);

    o1.x = fmaf(v1.x, c00, -v1.y * s00);
    o1.y = fmaf(v1.y, c00,  v1.x * s00);
    o1.z = fmaf(v1.z, c01, -v1.w * s01);
    o1.w = fmaf(v1.w, c01,  v1.z * s01);

    o2.x = fmaf(v2.x, c10, -v2.y * s10);
    o2.y = fmaf(v2.y, c10,  v2.x * s10);
    o2.z = fmaf(v2.z, c11, -v2.w * s11);
    o2.w = fmaf(v2.w, c11,  v2.z * s11);

    o3.x = fmaf(v3.x, c10, -v3.y * s10);
    o3.y = fmaf(v3.y, c10,  v3.x * s10);
    o3.z = fmaf(v3.z, c11, -v3.w * s11);
    o3.w = fmaf(v3.w, c11,  v3.z * s11);

    __stcs(&out[f0],       o0);
    __stcs(&out[f0 + 128], o1);
    __stcs(&out[f0 + 256], o2);
    __stcs(&out[f0 + 384], o3);
}

extern "C" void kernel_launch(void* const* d_in, const int* in_sizes, int n_in,
                              void* d_out, int out_size) {
    const float4* x = (const float4*)d_in[0];
    const int* grid_sizes = (const int*)d_in[1];
    float4* out = (float4*)d_out;

    int total4 = in_sizes[0] / 4;            // 8,388,608 float4
    int nblocks = total4 / 512;              // 16384 blocks of 128 threads
    rope2d_kernel<<<nblocks, 128>>>(x, grid_sizes, out);
}